// round 14
// baseline (speedup 1.0000x reference)
#include <cuda_runtime.h>
#include <cuda_fp16.h>
#include <cstdint>
#include <cstddef>

#define NB      2
#define LQ      2048
#define LK      2048
#define DMODEL  1024
#define DK      64
#define DHEAD   16
#define DEPTH   1024
#define MROWS   4096

// Scratch (__device__ globals; allocation-free rule)
__device__ float  g_Q [(size_t)MROWS * DEPTH];      // fp32 (split to hi/lo in attention)
__device__ __half g_Kh[(size_t)MROWS * DEPTH];      // [token][1024], fp16
__device__ __half g_Vh[(size_t)MROWS * DEPTH];      // TRANSPOSED [b][h][64 dim][2048 key], fp16
__device__ __half g_Oh[(size_t)MROWS * DEPTH];      // attention out, fp16
__device__ __half g_Xh[(size_t)MROWS * DMODEL];     // fp16-rounded x
__device__ __half g_Yh[(size_t)MROWS * DMODEL];     // fp16-rounded y
__device__ __half g_Wh[4][(size_t)DMODEL * DEPTH];  // fp16 W^T: [n][k]

// ---------------------------------------------------------------------------
// Helpers
// ---------------------------------------------------------------------------
__device__ __forceinline__ uint32_t smem_u32(const void* p) {
    uint32_t a;
    asm("{ .reg .u64 t; cvta.to.shared.u64 t, %1; cvt.u32.u64 %0, t; }"
        : "=r"(a) : "l"(p));
    return a;
}
__device__ __forceinline__ void cp16(uint32_t dst, const void* src) {
    asm volatile("cp.async.cg.shared.global [%0], [%1], 16;" :: "r"(dst), "l"(src));
}
__device__ __forceinline__ void cp_commit() { asm volatile("cp.async.commit_group;"); }
__device__ __forceinline__ void cp_wait1()  { asm volatile("cp.async.wait_group 1;" ::: "memory"); }
__device__ __forceinline__ void cp_wait0()  { asm volatile("cp.async.wait_group 0;" ::: "memory"); }

// m16n8k16 fp16 mma, fp32 accum: D = A*B + D
__device__ __forceinline__ void mma_f16(float& c0, float& c1, float& c2, float& c3,
                                        uint32_t a0, uint32_t a1, uint32_t a2, uint32_t a3,
                                        uint32_t b0, uint32_t b1) {
    asm volatile("mma.sync.aligned.m16n8k16.row.col.f32.f16.f16.f32 "
                 "{%0,%1,%2,%3}, {%4,%5,%6,%7}, {%8,%9}, {%0,%1,%2,%3};"
                 : "+f"(c0), "+f"(c1), "+f"(c2), "+f"(c3)
                 : "r"(a0), "r"(a1), "r"(a2), "r"(a3), "r"(b0), "r"(b1));
}
__device__ __forceinline__ void ldmx4(uint32_t* d, uint32_t addr) {
    asm volatile("ldmatrix.sync.aligned.m8n8.x4.shared.b16 {%0,%1,%2,%3}, [%4];"
                 : "=r"(d[0]), "=r"(d[1]), "=r"(d[2]), "=r"(d[3]) : "r"(addr));
}
// split a float2 into packed fp16 hi and lo-residual half2's
__device__ __forceinline__ void split2(float x, float y, uint32_t& hi, uint32_t& lo) {
    __half hx = __float2half_rn(x), hy = __float2half_rn(y);
    __half2 h = __halves2half2(hx, hy);
    __half2 l = __halves2half2(__float2half_rn(x - __half2float(hx)),
                               __float2half_rn(y - __half2float(hy)));
    hi = *(uint32_t*)&h;
    lo = *(uint32_t*)&l;
}

// ---------------------------------------------------------------------------
// Unified prepass: blocks 0..8191 round x/y to fp16; 8192..12287 W^T fp16.
// ---------------------------------------------------------------------------
__global__ __launch_bounds__(256) void prep_kernel(
    const float* __restrict__ x, const float* __restrict__ y,
    const float* __restrict__ w0, const float* __restrict__ w1,
    const float* __restrict__ w2, const float* __restrict__ w3)
{
    __shared__ float tile[32][33];
    const int bid = blockIdx.x;
    const int tid = threadIdx.x;
    if (bid < 8192) {
        const float* in = (bid < 4096) ? x : y;
        __half* out = (bid < 4096) ? g_Xh : g_Yh;
        size_t i = (size_t)(bid & 4095) * 256 + tid;
        float4 v = ((const float4*)in)[i];
        __half2 h0 = __floats2half2_rn(v.x, v.y);
        __half2 h1 = __floats2half2_rn(v.z, v.w);
        uint2 u; u.x = *(uint32_t*)&h0; u.y = *(uint32_t*)&h1;
        ((uint2*)out)[i] = u;
    } else {
        const int w = bid - 8192;
        const int widx = w >> 10;
        const int tile_id = w & 1023;
        const int bx = tile_id & 31, by = tile_id >> 5;   // n-tile, k-tile
        const float* W;
        switch (widx) { case 0: W = w0; break; case 1: W = w1; break;
                        case 2: W = w2; break; default: W = w3; break; }
        const int tx = tid & 31, ty = tid >> 5;           // 32 x 8
#pragma unroll
        for (int i = 0; i < 4; i++)
            tile[ty + 8 * i][tx] = W[(size_t)(by * 32 + ty + 8 * i) * DEPTH + bx * 32 + tx];
        __syncthreads();
        __half* out = g_Wh[widx];
#pragma unroll
        for (int i = 0; i < 4; i++)
            out[(size_t)(bx * 32 + ty + 8 * i) * DMODEL + by * 32 + tx] =
                __float2half_rn(tile[tx][ty + 8 * i]);
    }
}

// ---------------------------------------------------------------------------
// fp16 m16n8k16 GEMM: C[4096,1024] = A[m][k] @ Wh[n][k]^T + bias.
// CTA 64x128, 8 warps in 2x4 grid, warp tile 32x32 (low regs -> 3 CTAs/SM).
// BK=32 halves, 2-stage cp.async, ldmatrix, stride 40 halves.
// a_sel: 0=g_Xh 1=g_Yh 2=g_Oh ; c_sel: 0=g_Q(f32) 1=g_Kh 2=g_Vh^T 3=Cout(f32)
// ---------------------------------------------------------------------------
#define HPAD  40
#define A_SGH (64 * HPAD)                   // halves per A stage
#define B_SGH (128 * HPAD)                  // halves per B stage
#define GEMM_SMEM ((2 * A_SGH + 2 * B_SGH) * 2)   // 30720 B

__global__ __launch_bounds__(256, 3) void gemm_tc_kernel(
    const float* __restrict__ bias, float* __restrict__ Cout,
    int a_sel, int widx, int c_sel)
{
    extern __shared__ __half hsm[];
    const __half* A = (a_sel == 0) ? g_Xh : (a_sel == 1) ? g_Yh : g_Oh;
    const __half* B = g_Wh[widx];

    __half* As = hsm;                   // 2 x A_SGH
    __half* Bs = hsm + 2 * A_SGH;       // 2 x B_SGH
    const uint32_t As_u = smem_u32(As), Bs_u = smem_u32(Bs);

    const int tid = threadIdx.x;
    const int wid = tid >> 5, lane = tid & 31;
    const int gid = lane >> 2, tig = lane & 3;
    const int g8 = lane >> 3, r8 = lane & 7;
    const int wr = wid >> 2, wc = wid & 3;       // 2 x 4 warp grid, tile 32x32
    const int m0 = blockIdx.y * 64, n0 = blockIdx.x * 128;

    // cp.async: A 1 cp16/thread (64 rows x 4 segs); B 2 cp16/thread (128 rows x 2x16)
    const int a_row = tid >> 2, a_seg = tid & 3;
    const int b_row = tid >> 1, b_half = tid & 1;
    const __half* Ap = A + (size_t)(m0 + a_row) * DMODEL + a_seg * 8;
    const __half* Bp = B + (size_t)(n0 + b_row) * DMODEL + b_half * 16;
    const uint32_t a_dst = (uint32_t)(a_row * HPAD + a_seg * 8);
    const uint32_t b_dst = (uint32_t)(b_row * HPAD + b_half * 16);

    // ldmatrix fragment bases (halves)
    const uint32_t aA = As_u + (uint32_t)((wr * 32 + r8 + (g8 & 1) * 8) * HPAD + (g8 >> 1) * 8) * 2;
    const uint32_t aB = Bs_u + (uint32_t)((wc * 32 + r8 + (g8 >> 1) * 8) * HPAD + (g8 & 1) * 8) * 2;

#define LOAD_CHUNK(c) do {                                                     \
        uint32_t _sa = (uint32_t)(((c) & 1) * A_SGH);                          \
        uint32_t _sb = (uint32_t)(((c) & 1) * B_SGH);                          \
        cp16(As_u + (_sa + a_dst) * 2, Ap + (c) * 32);                         \
        cp16(Bs_u + (_sb + b_dst) * 2, Bp + (c) * 32);                         \
        cp16(Bs_u + (_sb + b_dst) * 2 + 16, Bp + (c) * 32 + 8);                \
    } while (0)

    float c[2][4][4];
#pragma unroll
    for (int mt = 0; mt < 2; mt++)
#pragma unroll
        for (int nt = 0; nt < 4; nt++)
#pragma unroll
            for (int r = 0; r < 4; r++) c[mt][nt][r] = 0.f;

    LOAD_CHUNK(0);
    cp_commit();

#pragma unroll 1
    for (int ch = 0; ch < 32; ch++) {
        if (ch + 1 < 32) {
            LOAD_CHUNK(ch + 1);
            cp_commit();
            cp_wait1();
        } else {
            cp_wait0();
        }
        __syncthreads();

        const uint32_t Ab = aA + (uint32_t)((ch & 1) * A_SGH) * 2;
        const uint32_t Bb = aB + (uint32_t)((ch & 1) * B_SGH) * 2;
#pragma unroll
        for (int ks = 0; ks < 2; ks++) {           // k16 per step
            uint32_t a[2][4], b[4][2];
#pragma unroll
            for (int mt = 0; mt < 2; mt++)
                ldmx4(a[mt], Ab + (uint32_t)(mt * 16 * HPAD + ks * 16) * 2);
#pragma unroll
            for (int ntp = 0; ntp < 2; ntp++) {
                uint32_t t[4];
                ldmx4(t, Bb + (uint32_t)(ntp * 16 * HPAD + ks * 16) * 2);
                b[2 * ntp][0] = t[0]; b[2 * ntp][1] = t[1];
                b[2 * ntp + 1][0] = t[2]; b[2 * ntp + 1][1] = t[3];
            }
#pragma unroll
            for (int mt = 0; mt < 2; mt++)
#pragma unroll
                for (int nt = 0; nt < 4; nt++)
                    mma_f16(c[mt][nt][0], c[mt][nt][1], c[mt][nt][2], c[mt][nt][3],
                            a[mt][0], a[mt][1], a[mt][2], a[mt][3],
                            b[nt][0], b[nt][1]);
        }
        __syncthreads();
    }
#undef LOAD_CHUNK

#pragma unroll
    for (int mt = 0; mt < 2; mt++) {
        const int row = m0 + wr * 32 + mt * 16 + gid;
#pragma unroll
        for (int nt = 0; nt < 4; nt++) {
            const int col = n0 + wc * 32 + nt * 8 + tig * 2;
            float2 bv = *(const float2*)&bias[col];
            float v0 = c[mt][nt][0] + bv.x, v1 = c[mt][nt][1] + bv.y;
            float v2 = c[mt][nt][2] + bv.x, v3 = c[mt][nt][3] + bv.y;
            if (c_sel == 0) {
                *(float2*)&g_Q[(size_t)row * DEPTH + col] = make_float2(v0, v1);
                *(float2*)&g_Q[(size_t)(row + 8) * DEPTH + col] = make_float2(v2, v3);
            } else if (c_sel == 1) {
                __half2 h0 = __floats2half2_rn(v0, v1);
                __half2 h1 = __floats2half2_rn(v2, v3);
                *(uint32_t*)&g_Kh[(size_t)row * DEPTH + col] = *(uint32_t*)&h0;
                *(uint32_t*)&g_Kh[(size_t)(row + 8) * DEPTH + col] = *(uint32_t*)&h1;
            } else if (c_sel == 2) {
                // V transposed [b][h][dim][key]
                const int bb = row >> 11, key = row & 2047;
                const int hh = col >> 6, dd = col & 63;
                __half* vb = g_Vh + (((size_t)bb * DHEAD + hh) * DK + dd) * LK;
                vb[key]          = __float2half_rn(v0);
                vb[LK + key]     = __float2half_rn(v1);
                vb[key + 8]      = __float2half_rn(v2);
                vb[LK + key + 8] = __float2half_rn(v3);
            } else {
                *(float2*)&Cout[(size_t)row * DEPTH + col] = make_float2(v0, v1);
                *(float2*)&Cout[(size_t)(row + 8) * DEPTH + col] = make_float2(v2, v3);
            }
        }
    }
}

// ---------------------------------------------------------------------------
// Flash attention, fp16 m16n8k16 mma. Q hi/lo 2-chain (exact S); P single
// chain (P in [0,1], fp16 rounding noise ~1e-4 in output — within budget).
// Smem layout unchanged from R12 (Plo region now unused; Qs staging overlaps
// Phi+gap only, K/V cp.async regions stay disjoint).
// ---------------------------------------------------------------------------
#define PSTR   72
#define PHI_B  0
#define KS_B   36864
#define VS_B   55296
#define KVSTG  9216
#define ATTN_SMEM 73728

__global__ __launch_bounds__(256) void flash_attn_tc_kernel()
{
    extern __shared__ char smc[];
    const int qt = (int)(gridDim.x - 1 - blockIdx.x);   // heavy tiles first
    const int h = blockIdx.y, b = blockIdx.z;
    const int tid = threadIdx.x;
    const int wq = tid >> 5, lane = tid & 31;
    const int gid = lane >> 2, tig = lane & 3;
    const int g8 = lane >> 3, r8 = lane & 7;
    const int q0 = qt * 128;

    const uint32_t sm_u = smem_u32(smc);
    float* Qs = (float*)smc;                         // [128][68] f32, start only
    __half* Phi = (__half*)(smc + PHI_B);
    const __half* Vt = g_Vh + ((size_t)b * DHEAD + h) * DK * LK;

    const int ntiles = 2 * qt + 2;

    // ldmatrix bases
    const uint32_t aPhi = sm_u + PHI_B +
        (uint32_t)((wq * 16 + r8 + (g8 & 1) * 8) * PSTR + (g8 >> 1) * 8) * 2;
    const uint32_t bfrag = (uint32_t)((r8 + (g8 >> 1) * 8) * PSTR + (g8 & 1) * 8) * 2;
    const uint32_t aK = sm_u + KS_B + bfrag;
    const uint32_t aV = sm_u + VS_B + bfrag;

    // --- K/V tile 0 (cp.async) ---
    {
#pragma unroll
        for (int i = 0; i < 2; i++) {
            int idx = i * 256 + tid;
            int row = idx >> 3, seg = idx & 7;
            const __half* kp = g_Kh + (size_t)(b * LK + row) * DEPTH + h * DK + seg * 8;
            const __half* vp = Vt + (size_t)row * LK + seg * 8;
            cp16(sm_u + KS_B + (uint32_t)(row * PSTR + seg * 8) * 2, kp);
            cp16(sm_u + VS_B + (uint32_t)(row * PSTR + seg * 8) * 2, vp);
        }
        cp_commit();
    }

    // --- stage Q (x fac) fp32 ---
    {
        const float fac = 0.125f;
#pragma unroll
        for (int i = 0; i < 8; i++) {
            int idx = i * 256 + tid;
            int row = idx >> 4, c4 = idx & 15;
            float4 v = *(const float4*)&g_Q[(size_t)(b * LQ + q0 + row) * DEPTH + h * DK + c4 * 4];
            float* d = &Qs[row * 68 + c4 * 4];
            d[0] = v.x * fac; d[1] = v.y * fac; d[2] = v.z * fac; d[3] = v.w * fac;
        }
    }
    __syncthreads();

    // --- extract Q hi/lo fragments (4 k16 chunks over d=64) ---
    uint32_t qhi[4][4], qlo[4][4];
    {
        const int r0 = wq * 16 + gid;
#pragma unroll
        for (int kc = 0; kc < 4; kc++) {
            float2 f0 = *(float2*)&Qs[r0 * 68 + kc * 16 + 2 * tig];
            float2 f1 = *(float2*)&Qs[(r0 + 8) * 68 + kc * 16 + 2 * tig];
            float2 f2 = *(float2*)&Qs[r0 * 68 + kc * 16 + 2 * tig + 8];
            float2 f3 = *(float2*)&Qs[(r0 + 8) * 68 + kc * 16 + 2 * tig + 8];
            split2(f0.x, f0.y, qhi[kc][0], qlo[kc][0]);
            split2(f1.x, f1.y, qhi[kc][1], qlo[kc][1]);
            split2(f2.x, f2.y, qhi[kc][2], qlo[kc][2]);
            split2(f3.x, f3.y, qhi[kc][3], qlo[kc][3]);
        }
    }
    __syncthreads();   // Qs region free for P

    float o[8][4];
#pragma unroll
    for (int nc = 0; nc < 8; nc++)
#pragma unroll
        for (int r = 0; r < 4; r++) o[nc][r] = 0.f;
    float m0 = -1e30f, m1 = -1e30f, l0 = 0.f, l1 = 0.f;

    const int qrow0 = q0 + wq * 16 + gid;
    const int qrow1 = qrow0 + 8;
    __half* PhiR0 = Phi + (wq * 16 + gid) * PSTR;
    __half* PhiR1 = PhiR0 + 8 * PSTR;

#pragma unroll 1
    for (int kt = 0; kt < ntiles; kt++) {
        cp_wait0();
        __syncthreads();
        const int cur = kt & 1;
        if (kt + 1 < ntiles) {
            const int k1 = (kt + 1) * 64, nb = (kt + 1) & 1;
#pragma unroll
            for (int i = 0; i < 2; i++) {
                int idx = i * 256 + tid;
                int row = idx >> 3, seg = idx & 7;
                const __half* kp = g_Kh + (size_t)(b * LK + k1 + row) * DEPTH + h * DK + seg * 8;
                const __half* vp = Vt + (size_t)row * LK + k1 + seg * 8;
                cp16(sm_u + KS_B + (uint32_t)(nb * KVSTG) + (uint32_t)(row * PSTR + seg * 8) * 2, kp);
                cp16(sm_u + VS_B + (uint32_t)(nb * KVSTG) + (uint32_t)(row * PSTR + seg * 8) * 2, vp);
            }
            cp_commit();
        }

        const uint32_t Kb = aK + (uint32_t)(cur * KVSTG);
        const uint32_t Vb = aV + (uint32_t)(cur * KVSTG);
        const int k0 = kt * 64;

        // ---- S = Q K^T (hi/lo chains) ----
        float s[8][4];
#pragma unroll
        for (int nc = 0; nc < 8; nc++)
#pragma unroll
            for (int r = 0; r < 4; r++) s[nc][r] = 0.f;
#pragma unroll
        for (int kc = 0; kc < 4; kc++) {
#pragma unroll
            for (int ncp = 0; ncp < 4; ncp++) {
                uint32_t t[4];
                ldmx4(t, Kb + (uint32_t)(ncp * 16 * PSTR + kc * 16) * 2);
                const int n0i = 2 * ncp, n1i = 2 * ncp + 1;
                mma_f16(s[n0i][0], s[n0i][1], s[n0i][2], s[n0i][3],
                        qhi[kc][0], qhi[kc][1], qhi[kc][2], qhi[kc][3], t[0], t[1]);
                mma_f16(s[n0i][0], s[n0i][1], s[n0i][2], s[n0i][3],
                        qlo[kc][0], qlo[kc][1], qlo[kc][2], qlo[kc][3], t[0], t[1]);
                mma_f16(s[n1i][0], s[n1i][1], s[n1i][2], s[n1i][3],
                        qhi[kc][0], qhi[kc][1], qhi[kc][2], qhi[kc][3], t[2], t[3]);
                mma_f16(s[n1i][0], s[n1i][1], s[n1i][2], s[n1i][3],
                        qlo[kc][0], qlo[kc][1], qlo[kc][2], qlo[kc][3], t[2], t[3]);
            }
        }

        // ---- causal mask (diagonal tiles only) ----
        if (kt >= 2 * qt) {
#pragma unroll
            for (int nc = 0; nc < 8; nc++) {
                int col = k0 + nc * 8 + 2 * tig;
                if (col > qrow0)     s[nc][0] = -1e30f;
                if (col + 1 > qrow0) s[nc][1] = -1e30f;
                if (col > qrow1)     s[nc][2] = -1e30f;
                if (col + 1 > qrow1) s[nc][3] = -1e30f;
            }
        }

        // ---- online softmax ----
        float mx0 = -1e30f, mx1 = -1e30f;
#pragma unroll
        for (int nc = 0; nc < 8; nc++) {
            mx0 = fmaxf(mx0, fmaxf(s[nc][0], s[nc][1]));
            mx1 = fmaxf(mx1, fmaxf(s[nc][2], s[nc][3]));
        }
        mx0 = fmaxf(mx0, __shfl_xor_sync(0xffffffffu, mx0, 1));
        mx0 = fmaxf(mx0, __shfl_xor_sync(0xffffffffu, mx0, 2));
        mx1 = fmaxf(mx1, __shfl_xor_sync(0xffffffffu, mx1, 1));
        mx1 = fmaxf(mx1, __shfl_xor_sync(0xffffffffu, mx1, 2));
        float mn0 = fmaxf(m0, mx0), mn1 = fmaxf(m1, mx1);
        float c0 = __expf(m0 - mn0), c1 = __expf(m1 - mn1);
        m0 = mn0; m1 = mn1;
        l0 *= c0; l1 *= c1;
#pragma unroll
        for (int nc = 0; nc < 8; nc++) {
            o[nc][0] *= c0; o[nc][1] *= c0;
            o[nc][2] *= c1; o[nc][3] *= c1;
        }
        float ls0 = 0.f, ls1 = 0.f;
#pragma unroll
        for (int nc = 0; nc < 8; nc++) {
            float p0 = __expf(s[nc][0] - mn0);
            float p1 = __expf(s[nc][1] - mn0);
            float p2 = __expf(s[nc][2] - mn1);
            float p3 = __expf(s[nc][3] - mn1);
            ls0 += p0 + p1; ls1 += p2 + p3;
            __half2 h0 = __floats2half2_rn(p0, p1);
            __half2 h1 = __floats2half2_rn(p2, p3);
            *(uint32_t*)&PhiR0[nc * 8 + 2 * tig] = *(uint32_t*)&h0;
            *(uint32_t*)&PhiR1[nc * 8 + 2 * tig] = *(uint32_t*)&h1;
        }
        l0 += ls0; l1 += ls1;
        __syncwarp();

        // ---- O += P V (single chain): 4 kc (keys) x 4 ncp (dims) ----
#pragma unroll
        for (int kc = 0; kc < 4; kc++) {
            uint32_t phi[4];
            ldmx4(phi, aPhi + (uint32_t)(kc * 16) * 2);
#pragma unroll
            for (int ncp = 0; ncp < 4; ncp++) {
                uint32_t t[4];
                ldmx4(t, Vb + (uint32_t)(ncp * 16 * PSTR + kc * 16) * 2);
                const int n0i = 2 * ncp, n1i = 2 * ncp + 1;
                mma_f16(o[n0i][0], o[n0i][1], o[n0i][2], o[n0i][3],
                        phi[0], phi[1], phi[2], phi[3], t[0], t[1]);
                mma_f16(o[n1i][0], o[n1i][1], o[n1i][2], o[n1i][3],
                        phi[0], phi[1], phi[2], phi[3], t[2], t[3]);
            }
        }
    }

    // ---- finalize: reduce l, normalize, store fp16 ----
    l0 += __shfl_xor_sync(0xffffffffu, l0, 1);
    l0 += __shfl_xor_sync(0xffffffffu, l0, 2);
    l1 += __shfl_xor_sync(0xffffffffu, l1, 1);
    l1 += __shfl_xor_sync(0xffffffffu, l1, 2);
    const float inv0 = 1.f / l0, inv1 = 1.f / l1;

    __half* o0 = g_Oh + (size_t)(b * LQ + qrow0) * DEPTH + h * DK;
    __half* o1 = g_Oh + (size_t)(b * LQ + qrow1) * DEPTH + h * DK;
#pragma unroll
    for (int nc = 0; nc < 8; nc++) {
        __half2 r0 = __floats2half2_rn(o[nc][0] * inv0, o[nc][1] * inv0);
        __half2 r1 = __floats2half2_rn(o[nc][2] * inv1, o[nc][3] * inv1);
        *(uint32_t*)&o0[nc * 8 + 2 * tig] = *(uint32_t*)&r0;
        *(uint32_t*)&o1[nc * 8 + 2 * tig] = *(uint32_t*)&r1;
    }
}

// ---------------------------------------------------------------------------
// Launch. Harness poison = launch 0, so attention = captured launch 5.
// ---------------------------------------------------------------------------
extern "C" void kernel_launch(void* const* d_in, const int* in_sizes, int n_in,
                              void* d_out, int out_size)
{
    const float* x  = (const float*)d_in[0];
    const float* y  = (const float*)d_in[1];
    // d_in[2] = causal mask — implicit
    const float* Wq = (const float*)d_in[3];
    const float* bq = (const float*)d_in[4];
    const float* Wk = (const float*)d_in[5];
    const float* bk = (const float*)d_in[6];
    const float* Wv = (const float*)d_in[7];
    const float* bv = (const float*)d_in[8];
    const float* Wo = (const float*)d_in[9];
    const float* bo = (const float*)d_in[10];
    float* out = (float*)d_out;

    cudaFuncSetAttribute(gemm_tc_kernel,
                         cudaFuncAttributeMaxDynamicSharedMemorySize, GEMM_SMEM);
    cudaFuncSetAttribute(flash_attn_tc_kernel,
                         cudaFuncAttributeMaxDynamicSharedMemorySize, ATTN_SMEM);

    prep_kernel<<<12288, 256>>>(x, y, Wq, Wk, Wv, Wo);                 // idx 1

    dim3 ggrid(DEPTH / 128, MROWS / 64);   // (8, 64) = 512 CTAs
    gemm_tc_kernel<<<ggrid, 256, GEMM_SMEM>>>(bq, nullptr, 0, 0, 0);   // 2: -> g_Q (f32)
    gemm_tc_kernel<<<ggrid, 256, GEMM_SMEM>>>(bk, nullptr, 1, 1, 1);   // 3: -> g_Kh
    gemm_tc_kernel<<<ggrid, 256, GEMM_SMEM>>>(bv, nullptr, 1, 2, 2);   // 4: -> g_Vh^T

    dim3 agrid(LQ / 128, DHEAD, NB);
    flash_attn_tc_kernel<<<agrid, 256, ATTN_SMEM>>>();                 // 5: -> g_Oh

    gemm_tc_kernel<<<ggrid, 256, GEMM_SMEM>>>(bo, out, 2, 3, 3);       // 6: -> out
}

// round 15
// speedup vs baseline: 1.1301x; 1.1301x over previous
#include <cuda_runtime.h>
#include <cuda_fp16.h>
#include <cstdint>
#include <cstddef>

#define NB      2
#define LQ      2048
#define LK      2048
#define DMODEL  1024
#define DK      64
#define DHEAD   16
#define DEPTH   1024
#define MROWS   4096

// Scratch (__device__ globals; allocation-free rule)
__device__ float  g_Q [(size_t)MROWS * DEPTH];      // fp32 (split to hi/lo in attention)
__device__ __half g_Kh[(size_t)MROWS * DEPTH];      // [token][1024], fp16
__device__ __half g_Vh[(size_t)MROWS * DEPTH];      // TRANSPOSED [b][h][64 dim][2048 key], fp16
__device__ __half g_Oh[(size_t)MROWS * DEPTH];      // attention out, fp16
__device__ __half g_Xh[(size_t)MROWS * DMODEL];     // fp16-rounded x
__device__ __half g_Yh[(size_t)MROWS * DMODEL];     // fp16-rounded y
__device__ __half g_Wh[4][(size_t)DMODEL * DEPTH];  // fp16 W^T: [n][k]

// ---------------------------------------------------------------------------
// Helpers
// ---------------------------------------------------------------------------
__device__ __forceinline__ uint32_t smem_u32(const void* p) {
    uint32_t a;
    asm("{ .reg .u64 t; cvta.to.shared.u64 t, %1; cvt.u32.u64 %0, t; }"
        : "=r"(a) : "l"(p));
    return a;
}
__device__ __forceinline__ void cp16(uint32_t dst, const void* src) {
    asm volatile("cp.async.cg.shared.global [%0], [%1], 16;" :: "r"(dst), "l"(src));
}
__device__ __forceinline__ void cp_commit() { asm volatile("cp.async.commit_group;"); }
__device__ __forceinline__ void cp_wait1()  { asm volatile("cp.async.wait_group 1;" ::: "memory"); }
__device__ __forceinline__ void cp_wait0()  { asm volatile("cp.async.wait_group 0;" ::: "memory"); }

// m16n8k16 fp16 mma, fp32 accum: D = A*B + D
__device__ __forceinline__ void mma_f16(float& c0, float& c1, float& c2, float& c3,
                                        uint32_t a0, uint32_t a1, uint32_t a2, uint32_t a3,
                                        uint32_t b0, uint32_t b1) {
    asm volatile("mma.sync.aligned.m16n8k16.row.col.f32.f16.f16.f32 "
                 "{%0,%1,%2,%3}, {%4,%5,%6,%7}, {%8,%9}, {%0,%1,%2,%3};"
                 : "+f"(c0), "+f"(c1), "+f"(c2), "+f"(c3)
                 : "r"(a0), "r"(a1), "r"(a2), "r"(a3), "r"(b0), "r"(b1));
}
__device__ __forceinline__ void ldmx4(uint32_t* d, uint32_t addr) {
    asm volatile("ldmatrix.sync.aligned.m8n8.x4.shared.b16 {%0,%1,%2,%3}, [%4];"
                 : "=r"(d[0]), "=r"(d[1]), "=r"(d[2]), "=r"(d[3]) : "r"(addr));
}
// split a float2 into packed fp16 hi and lo-residual half2's
__device__ __forceinline__ void split2(float x, float y, uint32_t& hi, uint32_t& lo) {
    __half hx = __float2half_rn(x), hy = __float2half_rn(y);
    __half2 h = __halves2half2(hx, hy);
    __half2 l = __halves2half2(__float2half_rn(x - __half2float(hx)),
                               __float2half_rn(y - __half2float(hy)));
    hi = *(uint32_t*)&h;
    lo = *(uint32_t*)&l;
}

// ---------------------------------------------------------------------------
// Unified prepass: blocks 0..8191 round x/y to fp16; 8192..12287 W^T fp16.
// ---------------------------------------------------------------------------
__global__ __launch_bounds__(256) void prep_kernel(
    const float* __restrict__ x, const float* __restrict__ y,
    const float* __restrict__ w0, const float* __restrict__ w1,
    const float* __restrict__ w2, const float* __restrict__ w3)
{
    __shared__ float tile[32][33];
    const int bid = blockIdx.x;
    const int tid = threadIdx.x;
    if (bid < 8192) {
        const float* in = (bid < 4096) ? x : y;
        __half* out = (bid < 4096) ? g_Xh : g_Yh;
        size_t i = (size_t)(bid & 4095) * 256 + tid;
        float4 v = ((const float4*)in)[i];
        __half2 h0 = __floats2half2_rn(v.x, v.y);
        __half2 h1 = __floats2half2_rn(v.z, v.w);
        uint2 u; u.x = *(uint32_t*)&h0; u.y = *(uint32_t*)&h1;
        ((uint2*)out)[i] = u;
    } else {
        const int w = bid - 8192;
        const int widx = w >> 10;
        const int tile_id = w & 1023;
        const int bx = tile_id & 31, by = tile_id >> 5;   // n-tile, k-tile
        const float* W;
        switch (widx) { case 0: W = w0; break; case 1: W = w1; break;
                        case 2: W = w2; break; default: W = w3; break; }
        const int tx = tid & 31, ty = tid >> 5;           // 32 x 8
#pragma unroll
        for (int i = 0; i < 4; i++)
            tile[ty + 8 * i][tx] = W[(size_t)(by * 32 + ty + 8 * i) * DEPTH + bx * 32 + tx];
        __syncthreads();
        __half* out = g_Wh[widx];
#pragma unroll
        for (int i = 0; i < 4; i++)
            out[(size_t)(bx * 32 + ty + 8 * i) * DMODEL + by * 32 + tx] =
                __float2half_rn(tile[tx][ty + 8 * i]);
    }
}

// ---------------------------------------------------------------------------
// fp16 m16n8k16 GEMM: C[4096,1024] = A[m][k] @ Wh[n][k]^T + bias.
// CTA 128x128, 8 warps (2x4 grid, warp tile 64x32) — the measured-best shape.
// BK=32 halves, THREE-stage cp.async, ONE sync per chunk, ldmatrix frags.
// a_sel: 0=g_Xh 1=g_Yh 2=g_Oh ; c_sel: 0=g_Q(f32) 1=g_Kh 2=g_Vh^T 3=Cout(f32)
// ---------------------------------------------------------------------------
#define HPAD 40
#define SGH  (128 * HPAD)                   // halves per stage (A or B)
#define GEMM_SMEM (6 * SGH * 2)             // 3 stages x (A+B), bytes = 61440

__global__ __launch_bounds__(256) void gemm_tc_kernel(
    const float* __restrict__ bias, float* __restrict__ Cout,
    int a_sel, int widx, int c_sel)
{
    extern __shared__ __half hsm[];
    const __half* A = (a_sel == 0) ? g_Xh : (a_sel == 1) ? g_Yh : g_Oh;
    const __half* B = g_Wh[widx];

    __half* As = hsm;                   // 3 x SGH
    __half* Bs = hsm + 3 * SGH;         // 3 x SGH
    const uint32_t As_u = smem_u32(As), Bs_u = smem_u32(Bs);

    const int tid = threadIdx.x;
    const int wid = tid >> 5, lane = tid & 31;
    const int gid = lane >> 2, tig = lane & 3;
    const int g8 = lane >> 3, r8 = lane & 7;
    const int wr = wid >> 2, wc = wid & 3;     // 2 x 4 warp grid: warp tile 64x32
    const int m0 = blockIdx.y * 128, n0 = blockIdx.x * 128;

    // cp.async: 2 threads per row, 16 halves (32B = 2 cp16) each
    const int lrow = tid >> 1, lofs = (tid & 1) * 16;
    const __half* Arow = A + (size_t)(m0 + lrow) * DMODEL + lofs;
    const __half* Brow = B + (size_t)(n0 + lrow) * DMODEL + lofs;
    const uint32_t ldst = (uint32_t)(lrow * HPAD + lofs);   // halves

    // ldmatrix fragment bases (halves)
    const uint32_t aA = As_u + (uint32_t)((wr * 64 + r8 + (g8 & 1) * 8) * HPAD + (g8 >> 1) * 8) * 2;
    const uint32_t aB = Bs_u + (uint32_t)((wc * 32 + r8 + (g8 >> 1) * 8) * HPAD + (g8 & 1) * 8) * 2;

#define LOAD_CHUNK(c) do {                                                     \
        uint32_t _st = (uint32_t)(((c) % 3) * SGH);                            \
        uint32_t _ad = As_u + (_st + ldst) * 2;                                \
        uint32_t _bd = Bs_u + (_st + ldst) * 2;                                \
        const __half* _ap = Arow + (c) * 32;                                   \
        const __half* _bp = Brow + (c) * 32;                                   \
        cp16(_ad, _ap); cp16(_ad + 16, _ap + 8);                               \
        cp16(_bd, _bp); cp16(_bd + 16, _bp + 8);                               \
    } while (0)

    float c[4][4][4];
#pragma unroll
    for (int mt = 0; mt < 4; mt++)
#pragma unroll
        for (int nt = 0; nt < 4; nt++)
#pragma unroll
            for (int r = 0; r < 4; r++) c[mt][nt][r] = 0.f;

    LOAD_CHUNK(0); cp_commit();
    LOAD_CHUNK(1); cp_commit();

#pragma unroll 1
    for (int ch = 0; ch < 32; ch++) {
        if (ch < 31) cp_wait1(); else cp_wait0();
        __syncthreads();                       // single barrier per chunk
        if (ch + 2 < 32) { LOAD_CHUNK(ch + 2); cp_commit(); }

        const uint32_t Ab = aA + (uint32_t)((ch % 3) * SGH) * 2;
        const uint32_t Bb = aB + (uint32_t)((ch % 3) * SGH) * 2;
#pragma unroll
        for (int ks = 0; ks < 2; ks++) {           // k16 per step
            uint32_t a[4][4], b[4][2];
#pragma unroll
            for (int mt = 0; mt < 4; mt++)
                ldmx4(a[mt], Ab + (uint32_t)(mt * 16 * HPAD + ks * 16) * 2);
#pragma unroll
            for (int ntp = 0; ntp < 2; ntp++) {
                uint32_t t[4];
                ldmx4(t, Bb + (uint32_t)(ntp * 16 * HPAD + ks * 16) * 2);
                b[2 * ntp][0] = t[0]; b[2 * ntp][1] = t[1];
                b[2 * ntp + 1][0] = t[2]; b[2 * ntp + 1][1] = t[3];
            }
#pragma unroll
            for (int mt = 0; mt < 4; mt++)
#pragma unroll
                for (int nt = 0; nt < 4; nt++)
                    mma_f16(c[mt][nt][0], c[mt][nt][1], c[mt][nt][2], c[mt][nt][3],
                            a[mt][0], a[mt][1], a[mt][2], a[mt][3],
                            b[nt][0], b[nt][1]);
        }
    }
#undef LOAD_CHUNK

#pragma unroll
    for (int mt = 0; mt < 4; mt++) {
        const int row = m0 + wr * 64 + mt * 16 + gid;
#pragma unroll
        for (int nt = 0; nt < 4; nt++) {
            const int col = n0 + wc * 32 + nt * 8 + tig * 2;
            float2 bv = *(const float2*)&bias[col];
            float v0 = c[mt][nt][0] + bv.x, v1 = c[mt][nt][1] + bv.y;
            float v2 = c[mt][nt][2] + bv.x, v3 = c[mt][nt][3] + bv.y;
            if (c_sel == 0) {
                *(float2*)&g_Q[(size_t)row * DEPTH + col] = make_float2(v0, v1);
                *(float2*)&g_Q[(size_t)(row + 8) * DEPTH + col] = make_float2(v2, v3);
            } else if (c_sel == 1) {
                __half2 h0 = __floats2half2_rn(v0, v1);
                __half2 h1 = __floats2half2_rn(v2, v3);
                *(uint32_t*)&g_Kh[(size_t)row * DEPTH + col] = *(uint32_t*)&h0;
                *(uint32_t*)&g_Kh[(size_t)(row + 8) * DEPTH + col] = *(uint32_t*)&h1;
            } else if (c_sel == 2) {
                // V transposed [b][h][dim][key]
                const int bb = row >> 11, key = row & 2047;
                const int hh = col >> 6, dd = col & 63;
                __half* vb = g_Vh + (((size_t)bb * DHEAD + hh) * DK + dd) * LK;
                vb[key]          = __float2half_rn(v0);
                vb[LK + key]     = __float2half_rn(v1);
                vb[key + 8]      = __float2half_rn(v2);
                vb[LK + key + 8] = __float2half_rn(v3);
            } else {
                *(float2*)&Cout[(size_t)row * DEPTH + col] = make_float2(v0, v1);
                *(float2*)&Cout[(size_t)(row + 8) * DEPTH + col] = make_float2(v2, v3);
            }
        }
    }
}

// ---------------------------------------------------------------------------
// Flash attention (unchanged from R13): fp16 mma, Q hi/lo, P single chain.
// ---------------------------------------------------------------------------
#define PSTR   72
#define PHI_B  0
#define KS_B   36864
#define VS_B   55296
#define KVSTG  9216
#define ATTN_SMEM 73728

__global__ __launch_bounds__(256) void flash_attn_tc_kernel()
{
    extern __shared__ char smc[];
    const int qt = (int)(gridDim.x - 1 - blockIdx.x);   // heavy tiles first
    const int h = blockIdx.y, b = blockIdx.z;
    const int tid = threadIdx.x;
    const int wq = tid >> 5, lane = tid & 31;
    const int gid = lane >> 2, tig = lane & 3;
    const int g8 = lane >> 3, r8 = lane & 7;
    const int q0 = qt * 128;

    const uint32_t sm_u = smem_u32(smc);
    float* Qs = (float*)smc;                         // [128][68] f32, start only
    __half* Phi = (__half*)(smc + PHI_B);
    const __half* Vt = g_Vh + ((size_t)b * DHEAD + h) * DK * LK;

    const int ntiles = 2 * qt + 2;

    const uint32_t aPhi = sm_u + PHI_B +
        (uint32_t)((wq * 16 + r8 + (g8 & 1) * 8) * PSTR + (g8 >> 1) * 8) * 2;
    const uint32_t bfrag = (uint32_t)((r8 + (g8 >> 1) * 8) * PSTR + (g8 & 1) * 8) * 2;
    const uint32_t aK = sm_u + KS_B + bfrag;
    const uint32_t aV = sm_u + VS_B + bfrag;

    // --- K/V tile 0 (cp.async) ---
    {
#pragma unroll
        for (int i = 0; i < 2; i++) {
            int idx = i * 256 + tid;
            int row = idx >> 3, seg = idx & 7;
            const __half* kp = g_Kh + (size_t)(b * LK + row) * DEPTH + h * DK + seg * 8;
            const __half* vp = Vt + (size_t)row * LK + seg * 8;
            cp16(sm_u + KS_B + (uint32_t)(row * PSTR + seg * 8) * 2, kp);
            cp16(sm_u + VS_B + (uint32_t)(row * PSTR + seg * 8) * 2, vp);
        }
        cp_commit();
    }

    // --- stage Q (x fac) fp32 ---
    {
        const float fac = 0.125f;
#pragma unroll
        for (int i = 0; i < 8; i++) {
            int idx = i * 256 + tid;
            int row = idx >> 4, c4 = idx & 15;
            float4 v = *(const float4*)&g_Q[(size_t)(b * LQ + q0 + row) * DEPTH + h * DK + c4 * 4];
            float* d = &Qs[row * 68 + c4 * 4];
            d[0] = v.x * fac; d[1] = v.y * fac; d[2] = v.z * fac; d[3] = v.w * fac;
        }
    }
    __syncthreads();

    // --- extract Q hi/lo fragments (4 k16 chunks over d=64) ---
    uint32_t qhi[4][4], qlo[4][4];
    {
        const int r0 = wq * 16 + gid;
#pragma unroll
        for (int kc = 0; kc < 4; kc++) {
            float2 f0 = *(float2*)&Qs[r0 * 68 + kc * 16 + 2 * tig];
            float2 f1 = *(float2*)&Qs[(r0 + 8) * 68 + kc * 16 + 2 * tig];
            float2 f2 = *(float2*)&Qs[r0 * 68 + kc * 16 + 2 * tig + 8];
            float2 f3 = *(float2*)&Qs[(r0 + 8) * 68 + kc * 16 + 2 * tig + 8];
            split2(f0.x, f0.y, qhi[kc][0], qlo[kc][0]);
            split2(f1.x, f1.y, qhi[kc][1], qlo[kc][1]);
            split2(f2.x, f2.y, qhi[kc][2], qlo[kc][2]);
            split2(f3.x, f3.y, qhi[kc][3], qlo[kc][3]);
        }
    }
    __syncthreads();   // Qs region free for P

    float o[8][4];
#pragma unroll
    for (int nc = 0; nc < 8; nc++)
#pragma unroll
        for (int r = 0; r < 4; r++) o[nc][r] = 0.f;
    float m0 = -1e30f, m1 = -1e30f, l0 = 0.f, l1 = 0.f;

    const int qrow0 = q0 + wq * 16 + gid;
    const int qrow1 = qrow0 + 8;
    __half* PhiR0 = Phi + (wq * 16 + gid) * PSTR;
    __half* PhiR1 = PhiR0 + 8 * PSTR;

#pragma unroll 1
    for (int kt = 0; kt < ntiles; kt++) {
        cp_wait0();
        __syncthreads();
        const int cur = kt & 1;
        if (kt + 1 < ntiles) {
            const int k1 = (kt + 1) * 64, nb = (kt + 1) & 1;
#pragma unroll
            for (int i = 0; i < 2; i++) {
                int idx = i * 256 + tid;
                int row = idx >> 3, seg = idx & 7;
                const __half* kp = g_Kh + (size_t)(b * LK + k1 + row) * DEPTH + h * DK + seg * 8;
                const __half* vp = Vt + (size_t)row * LK + k1 + seg * 8;
                cp16(sm_u + KS_B + (uint32_t)(nb * KVSTG) + (uint32_t)(row * PSTR + seg * 8) * 2, kp);
                cp16(sm_u + VS_B + (uint32_t)(nb * KVSTG) + (uint32_t)(row * PSTR + seg * 8) * 2, vp);
            }
            cp_commit();
        }

        const uint32_t Kb = aK + (uint32_t)(cur * KVSTG);
        const uint32_t Vb = aV + (uint32_t)(cur * KVSTG);
        const int k0 = kt * 64;

        // ---- S = Q K^T (hi/lo chains) ----
        float s[8][4];
#pragma unroll
        for (int nc = 0; nc < 8; nc++)
#pragma unroll
            for (int r = 0; r < 4; r++) s[nc][r] = 0.f;
#pragma unroll
        for (int kc = 0; kc < 4; kc++) {
#pragma unroll
            for (int ncp = 0; ncp < 4; ncp++) {
                uint32_t t[4];
                ldmx4(t, Kb + (uint32_t)(ncp * 16 * PSTR + kc * 16) * 2);
                const int n0i = 2 * ncp, n1i = 2 * ncp + 1;
                mma_f16(s[n0i][0], s[n0i][1], s[n0i][2], s[n0i][3],
                        qhi[kc][0], qhi[kc][1], qhi[kc][2], qhi[kc][3], t[0], t[1]);
                mma_f16(s[n0i][0], s[n0i][1], s[n0i][2], s[n0i][3],
                        qlo[kc][0], qlo[kc][1], qlo[kc][2], qlo[kc][3], t[0], t[1]);
                mma_f16(s[n1i][0], s[n1i][1], s[n1i][2], s[n1i][3],
                        qhi[kc][0], qhi[kc][1], qhi[kc][2], qhi[kc][3], t[2], t[3]);
                mma_f16(s[n1i][0], s[n1i][1], s[n1i][2], s[n1i][3],
                        qlo[kc][0], qlo[kc][1], qlo[kc][2], qlo[kc][3], t[2], t[3]);
            }
        }

        // ---- causal mask (diagonal tiles only) ----
        if (kt >= 2 * qt) {
#pragma unroll
            for (int nc = 0; nc < 8; nc++) {
                int col = k0 + nc * 8 + 2 * tig;
                if (col > qrow0)     s[nc][0] = -1e30f;
                if (col + 1 > qrow0) s[nc][1] = -1e30f;
                if (col > qrow1)     s[nc][2] = -1e30f;
                if (col + 1 > qrow1) s[nc][3] = -1e30f;
            }
        }

        // ---- online softmax ----
        float mx0 = -1e30f, mx1 = -1e30f;
#pragma unroll
        for (int nc = 0; nc < 8; nc++) {
            mx0 = fmaxf(mx0, fmaxf(s[nc][0], s[nc][1]));
            mx1 = fmaxf(mx1, fmaxf(s[nc][2], s[nc][3]));
        }
        mx0 = fmaxf(mx0, __shfl_xor_sync(0xffffffffu, mx0, 1));
        mx0 = fmaxf(mx0, __shfl_xor_sync(0xffffffffu, mx0, 2));
        mx1 = fmaxf(mx1, __shfl_xor_sync(0xffffffffu, mx1, 1));
        mx1 = fmaxf(mx1, __shfl_xor_sync(0xffffffffu, mx1, 2));
        float mn0 = fmaxf(m0, mx0), mn1 = fmaxf(m1, mx1);
        float c0 = __expf(m0 - mn0), c1 = __expf(m1 - mn1);
        m0 = mn0; m1 = mn1;
        l0 *= c0; l1 *= c1;
#pragma unroll
        for (int nc = 0; nc < 8; nc++) {
            o[nc][0] *= c0; o[nc][1] *= c0;
            o[nc][2] *= c1; o[nc][3] *= c1;
        }
        float ls0 = 0.f, ls1 = 0.f;
#pragma unroll
        for (int nc = 0; nc < 8; nc++) {
            float p0 = __expf(s[nc][0] - mn0);
            float p1 = __expf(s[nc][1] - mn0);
            float p2 = __expf(s[nc][2] - mn1);
            float p3 = __expf(s[nc][3] - mn1);
            ls0 += p0 + p1; ls1 += p2 + p3;
            __half2 h0 = __floats2half2_rn(p0, p1);
            __half2 h1 = __floats2half2_rn(p2, p3);
            *(uint32_t*)&PhiR0[nc * 8 + 2 * tig] = *(uint32_t*)&h0;
            *(uint32_t*)&PhiR1[nc * 8 + 2 * tig] = *(uint32_t*)&h1;
        }
        l0 += ls0; l1 += ls1;
        __syncwarp();

        // ---- O += P V (single chain): 4 kc (keys) x 4 ncp (dims) ----
#pragma unroll
        for (int kc = 0; kc < 4; kc++) {
            uint32_t phi[4];
            ldmx4(phi, aPhi + (uint32_t)(kc * 16) * 2);
#pragma unroll
            for (int ncp = 0; ncp < 4; ncp++) {
                uint32_t t[4];
                ldmx4(t, Vb + (uint32_t)(ncp * 16 * PSTR + kc * 16) * 2);
                const int n0i = 2 * ncp, n1i = 2 * ncp + 1;
                mma_f16(o[n0i][0], o[n0i][1], o[n0i][2], o[n0i][3],
                        phi[0], phi[1], phi[2], phi[3], t[0], t[1]);
                mma_f16(o[n1i][0], o[n1i][1], o[n1i][2], o[n1i][3],
                        phi[0], phi[1], phi[2], phi[3], t[2], t[3]);
            }
        }
    }

    // ---- finalize: reduce l, normalize, store fp16 ----
    l0 += __shfl_xor_sync(0xffffffffu, l0, 1);
    l0 += __shfl_xor_sync(0xffffffffu, l0, 2);
    l1 += __shfl_xor_sync(0xffffffffu, l1, 1);
    l1 += __shfl_xor_sync(0xffffffffu, l1, 2);
    const float inv0 = 1.f / l0, inv1 = 1.f / l1;

    __half* o0 = g_Oh + (size_t)(b * LQ + qrow0) * DEPTH + h * DK;
    __half* o1 = g_Oh + (size_t)(b * LQ + qrow1) * DEPTH + h * DK;
#pragma unroll
    for (int nc = 0; nc < 8; nc++) {
        __half2 r0 = __floats2half2_rn(o[nc][0] * inv0, o[nc][1] * inv0);
        __half2 r1 = __floats2half2_rn(o[nc][2] * inv1, o[nc][3] * inv1);
        *(uint32_t*)&o0[nc * 8 + 2 * tig] = *(uint32_t*)&r0;
        *(uint32_t*)&o1[nc * 8 + 2 * tig] = *(uint32_t*)&r1;
    }
}

// ---------------------------------------------------------------------------
// Launch. Harness poison = launch 0, so attention = captured launch 5.
// ---------------------------------------------------------------------------
extern "C" void kernel_launch(void* const* d_in, const int* in_sizes, int n_in,
                              void* d_out, int out_size)
{
    const float* x  = (const float*)d_in[0];
    const float* y  = (const float*)d_in[1];
    // d_in[2] = causal mask — implicit
    const float* Wq = (const float*)d_in[3];
    const float* bq = (const float*)d_in[4];
    const float* Wk = (const float*)d_in[5];
    const float* bk = (const float*)d_in[6];
    const float* Wv = (const float*)d_in[7];
    const float* bv = (const float*)d_in[8];
    const float* Wo = (const float*)d_in[9];
    const float* bo = (const float*)d_in[10];
    float* out = (float*)d_out;

    cudaFuncSetAttribute(gemm_tc_kernel,
                         cudaFuncAttributeMaxDynamicSharedMemorySize, GEMM_SMEM);
    cudaFuncSetAttribute(flash_attn_tc_kernel,
                         cudaFuncAttributeMaxDynamicSharedMemorySize, ATTN_SMEM);

    prep_kernel<<<12288, 256>>>(x, y, Wq, Wk, Wv, Wo);                 // idx 1

    dim3 ggrid(DEPTH / 128, MROWS / 128);   // (8, 32) = 256 CTAs
    gemm_tc_kernel<<<ggrid, 256, GEMM_SMEM>>>(bq, nullptr, 0, 0, 0);   // 2: -> g_Q (f32)
    gemm_tc_kernel<<<ggrid, 256, GEMM_SMEM>>>(bk, nullptr, 1, 1, 1);   // 3: -> g_Kh
    gemm_tc_kernel<<<ggrid, 256, GEMM_SMEM>>>(bv, nullptr, 1, 2, 2);   // 4: -> g_Vh^T

    dim3 agrid(LQ / 128, DHEAD, NB);
    flash_attn_tc_kernel<<<agrid, 256, ATTN_SMEM>>>();                 // 5: -> g_Oh

    gemm_tc_kernel<<<ggrid, 256, GEMM_SMEM>>>(bo, out, 2, 3, 3);       // 6: -> out
}

// round 16
// speedup vs baseline: 1.1397x; 1.0085x over previous
#include <cuda_runtime.h>
#include <cuda_fp16.h>
#include <cstdint>
#include <cstddef>

#define NB      2
#define LQ      2048
#define LK      2048
#define DMODEL  1024
#define DK      64
#define DHEAD   16
#define DEPTH   1024
#define MROWS   4096

// Scratch (__device__ globals; allocation-free rule)
__device__ float  g_Q [(size_t)MROWS * DEPTH];      // fp32 (split to hi/lo in attention)
__device__ __half g_Kh[(size_t)MROWS * DEPTH];      // [token][1024], fp16
__device__ __half g_Vh[(size_t)MROWS * DEPTH];      // TRANSPOSED [b][h][64 dim][2048 key], fp16
__device__ __half g_Oh[(size_t)MROWS * DEPTH];      // attention out, fp16
__device__ __half g_Xh[(size_t)MROWS * DMODEL];     // fp16-rounded x
__device__ __half g_Yh[(size_t)MROWS * DMODEL];     // fp16-rounded y
__device__ __half g_Wh[4][(size_t)DMODEL * DEPTH];  // fp16 W^T: [n][k]

// ---------------------------------------------------------------------------
// Helpers
// ---------------------------------------------------------------------------
__device__ __forceinline__ uint32_t smem_u32(const void* p) {
    uint32_t a;
    asm("{ .reg .u64 t; cvta.to.shared.u64 t, %1; cvt.u32.u64 %0, t; }"
        : "=r"(a) : "l"(p));
    return a;
}
__device__ __forceinline__ void cp16(uint32_t dst, const void* src) {
    asm volatile("cp.async.cg.shared.global [%0], [%1], 16;" :: "r"(dst), "l"(src));
}
__device__ __forceinline__ void cp_commit() { asm volatile("cp.async.commit_group;"); }
__device__ __forceinline__ void cp_wait1()  { asm volatile("cp.async.wait_group 1;" ::: "memory"); }
__device__ __forceinline__ void cp_wait0()  { asm volatile("cp.async.wait_group 0;" ::: "memory"); }

// m16n8k16 fp16 mma, fp32 accum: D = A*B + D
__device__ __forceinline__ void mma_f16(float& c0, float& c1, float& c2, float& c3,
                                        uint32_t a0, uint32_t a1, uint32_t a2, uint32_t a3,
                                        uint32_t b0, uint32_t b1) {
    asm volatile("mma.sync.aligned.m16n8k16.row.col.f32.f16.f16.f32 "
                 "{%0,%1,%2,%3}, {%4,%5,%6,%7}, {%8,%9}, {%0,%1,%2,%3};"
                 : "+f"(c0), "+f"(c1), "+f"(c2), "+f"(c3)
                 : "r"(a0), "r"(a1), "r"(a2), "r"(a3), "r"(b0), "r"(b1));
}
__device__ __forceinline__ void ldmx4(uint32_t* d, uint32_t addr) {
    asm volatile("ldmatrix.sync.aligned.m8n8.x4.shared.b16 {%0,%1,%2,%3}, [%4];"
                 : "=r"(d[0]), "=r"(d[1]), "=r"(d[2]), "=r"(d[3]) : "r"(addr));
}
// split a float2 into packed fp16 hi and lo-residual half2's
__device__ __forceinline__ void split2(float x, float y, uint32_t& hi, uint32_t& lo) {
    __half hx = __float2half_rn(x), hy = __float2half_rn(y);
    __half2 h = __halves2half2(hx, hy);
    __half2 l = __halves2half2(__float2half_rn(x - __half2float(hx)),
                               __float2half_rn(y - __half2float(hy)));
    hi = *(uint32_t*)&h;
    lo = *(uint32_t*)&l;
}

// ---------------------------------------------------------------------------
// Unified prepass: blocks 0..8191 round x/y to fp16; 8192..12287 W^T fp16.
// ---------------------------------------------------------------------------
__global__ __launch_bounds__(256) void prep_kernel(
    const float* __restrict__ x, const float* __restrict__ y,
    const float* __restrict__ w0, const float* __restrict__ w1,
    const float* __restrict__ w2, const float* __restrict__ w3)
{
    __shared__ float tile[32][33];
    const int bid = blockIdx.x;
    const int tid = threadIdx.x;
    if (bid < 8192) {
        const float* in = (bid < 4096) ? x : y;
        __half* out = (bid < 4096) ? g_Xh : g_Yh;
        size_t i = (size_t)(bid & 4095) * 256 + tid;
        float4 v = ((const float4*)in)[i];
        __half2 h0 = __floats2half2_rn(v.x, v.y);
        __half2 h1 = __floats2half2_rn(v.z, v.w);
        uint2 u; u.x = *(uint32_t*)&h0; u.y = *(uint32_t*)&h1;
        ((uint2*)out)[i] = u;
    } else {
        const int w = bid - 8192;
        const int widx = w >> 10;
        const int tile_id = w & 1023;
        const int bx = tile_id & 31, by = tile_id >> 5;   // n-tile, k-tile
        const float* W;
        switch (widx) { case 0: W = w0; break; case 1: W = w1; break;
                        case 2: W = w2; break; default: W = w3; break; }
        const int tx = tid & 31, ty = tid >> 5;           // 32 x 8
#pragma unroll
        for (int i = 0; i < 4; i++)
            tile[ty + 8 * i][tx] = W[(size_t)(by * 32 + ty + 8 * i) * DEPTH + bx * 32 + tx];
        __syncthreads();
        __half* out = g_Wh[widx];
#pragma unroll
        for (int i = 0; i < 4; i++)
            out[(size_t)(bx * 32 + ty + 8 * i) * DMODEL + by * 32 + tx] =
                __float2half_rn(tile[tx][ty + 8 * i]);
    }
}

// ---------------------------------------------------------------------------
// fp16 m16n8k16 GEMM body (R15 measured-best config):
// CTA 128x128, 8 warps (2x4 grid, warp tile 64x32), BK=32 halves,
// 3-stage cp.async, 1 sync per chunk, ldmatrix frags, stride 40 halves.
// c_sel: 0=g_Q(f32) 1=g_Kh 2=g_Vh^T 3=Cout(f32)
// ---------------------------------------------------------------------------
#define HPAD 40
#define SGH  (128 * HPAD)                   // halves per stage (A or B)
#define GEMM_SMEM (6 * SGH * 2)             // 3 stages x (A+B), bytes = 61440

__device__ __forceinline__ void gemm_body(
    const __half* __restrict__ A, const __half* __restrict__ B,
    const float* __restrict__ bias, float* __restrict__ Cout, int c_sel,
    __half* hsm)
{
    __half* As = hsm;                   // 3 x SGH
    __half* Bs = hsm + 3 * SGH;         // 3 x SGH
    const uint32_t As_u = smem_u32(As), Bs_u = smem_u32(Bs);

    const int tid = threadIdx.x;
    const int wid = tid >> 5, lane = tid & 31;
    const int gid = lane >> 2, tig = lane & 3;
    const int g8 = lane >> 3, r8 = lane & 7;
    const int wr = wid >> 2, wc = wid & 3;     // 2 x 4 warp grid: warp tile 64x32
    const int m0 = blockIdx.y * 128, n0 = blockIdx.x * 128;

    // cp.async: 2 threads per row, 16 halves (32B = 2 cp16) each
    const int lrow = tid >> 1, lofs = (tid & 1) * 16;
    const __half* Arow = A + (size_t)(m0 + lrow) * DMODEL + lofs;
    const __half* Brow = B + (size_t)(n0 + lrow) * DMODEL + lofs;
    const uint32_t ldst = (uint32_t)(lrow * HPAD + lofs);   // halves

    // ldmatrix fragment bases (halves)
    const uint32_t aA = As_u + (uint32_t)((wr * 64 + r8 + (g8 & 1) * 8) * HPAD + (g8 >> 1) * 8) * 2;
    const uint32_t aB = Bs_u + (uint32_t)((wc * 32 + r8 + (g8 >> 1) * 8) * HPAD + (g8 & 1) * 8) * 2;

#define LOAD_CHUNK(c) do {                                                     \
        uint32_t _st = (uint32_t)(((c) % 3) * SGH);                            \
        uint32_t _ad = As_u + (_st + ldst) * 2;                                \
        uint32_t _bd = Bs_u + (_st + ldst) * 2;                                \
        const __half* _ap = Arow + (c) * 32;                                   \
        const __half* _bp = Brow + (c) * 32;                                   \
        cp16(_ad, _ap); cp16(_ad + 16, _ap + 8);                               \
        cp16(_bd, _bp); cp16(_bd + 16, _bp + 8);                               \
    } while (0)

    float c[4][4][4];
#pragma unroll
    for (int mt = 0; mt < 4; mt++)
#pragma unroll
        for (int nt = 0; nt < 4; nt++)
#pragma unroll
            for (int r = 0; r < 4; r++) c[mt][nt][r] = 0.f;

    LOAD_CHUNK(0); cp_commit();
    LOAD_CHUNK(1); cp_commit();

#pragma unroll 1
    for (int ch = 0; ch < 32; ch++) {
        if (ch < 31) cp_wait1(); else cp_wait0();
        __syncthreads();                       // single barrier per chunk
        if (ch + 2 < 32) { LOAD_CHUNK(ch + 2); cp_commit(); }

        const uint32_t Ab = aA + (uint32_t)((ch % 3) * SGH) * 2;
        const uint32_t Bb = aB + (uint32_t)((ch % 3) * SGH) * 2;
#pragma unroll
        for (int ks = 0; ks < 2; ks++) {           // k16 per step
            uint32_t a[4][4], b[4][2];
#pragma unroll
            for (int mt = 0; mt < 4; mt++)
                ldmx4(a[mt], Ab + (uint32_t)(mt * 16 * HPAD + ks * 16) * 2);
#pragma unroll
            for (int ntp = 0; ntp < 2; ntp++) {
                uint32_t t[4];
                ldmx4(t, Bb + (uint32_t)(ntp * 16 * HPAD + ks * 16) * 2);
                b[2 * ntp][0] = t[0]; b[2 * ntp][1] = t[1];
                b[2 * ntp + 1][0] = t[2]; b[2 * ntp + 1][1] = t[3];
            }
#pragma unroll
            for (int mt = 0; mt < 4; mt++)
#pragma unroll
                for (int nt = 0; nt < 4; nt++)
                    mma_f16(c[mt][nt][0], c[mt][nt][1], c[mt][nt][2], c[mt][nt][3],
                            a[mt][0], a[mt][1], a[mt][2], a[mt][3],
                            b[nt][0], b[nt][1]);
        }
    }
#undef LOAD_CHUNK

#pragma unroll
    for (int mt = 0; mt < 4; mt++) {
        const int row = m0 + wr * 64 + mt * 16 + gid;
#pragma unroll
        for (int nt = 0; nt < 4; nt++) {
            const int col = n0 + wc * 32 + nt * 8 + tig * 2;
            float2 bv = *(const float2*)&bias[col];
            float v0 = c[mt][nt][0] + bv.x, v1 = c[mt][nt][1] + bv.y;
            float v2 = c[mt][nt][2] + bv.x, v3 = c[mt][nt][3] + bv.y;
            if (c_sel == 0) {
                *(float2*)&g_Q[(size_t)row * DEPTH + col] = make_float2(v0, v1);
                *(float2*)&g_Q[(size_t)(row + 8) * DEPTH + col] = make_float2(v2, v3);
            } else if (c_sel == 1) {
                __half2 h0 = __floats2half2_rn(v0, v1);
                __half2 h1 = __floats2half2_rn(v2, v3);
                *(uint32_t*)&g_Kh[(size_t)row * DEPTH + col] = *(uint32_t*)&h0;
                *(uint32_t*)&g_Kh[(size_t)(row + 8) * DEPTH + col] = *(uint32_t*)&h1;
            } else if (c_sel == 2) {
                // V transposed [b][h][dim][key]
                const int bb = row >> 11, key = row & 2047;
                const int hh = col >> 6, dd = col & 63;
                __half* vb = g_Vh + (((size_t)bb * DHEAD + hh) * DK + dd) * LK;
                vb[key]          = __float2half_rn(v0);
                vb[LK + key]     = __float2half_rn(v1);
                vb[key + 8]      = __float2half_rn(v2);
                vb[LK + key + 8] = __float2half_rn(v3);
            } else {
                *(float2*)&Cout[(size_t)row * DEPTH + col] = make_float2(v0, v1);
                *(float2*)&Cout[(size_t)(row + 8) * DEPTH + col] = make_float2(v2, v3);
            }
        }
    }
}

// Single-output GEMM (Q projection / O projection)
__global__ __launch_bounds__(256) void gemm_tc_kernel(
    const float* __restrict__ bias, float* __restrict__ Cout,
    int a_sel, int widx, int c_sel)
{
    extern __shared__ __half hsm[];
    const __half* A = (a_sel == 0) ? g_Xh : (a_sel == 1) ? g_Yh : g_Oh;
    gemm_body(A, g_Wh[widx], bias, Cout, c_sel, hsm);
}

// Fused K+V projections: blockIdx.z = 0 -> K (g_Kh), 1 -> V (g_Vh^T)
__global__ __launch_bounds__(256) void gemm_kv_kernel(
    const float* __restrict__ bk, const float* __restrict__ bv)
{
    extern __shared__ __half hsm[];
    const int z = blockIdx.z;
    gemm_body(g_Yh, g_Wh[1 + z], z ? bv : bk, nullptr, 1 + z, hsm);
}

// ---------------------------------------------------------------------------
// Flash attention (unchanged from R13/R15): fp16 mma, Q hi/lo, P single chain.
// ---------------------------------------------------------------------------
#define PSTR   72
#define PHI_B  0
#define KS_B   36864
#define VS_B   55296
#define KVSTG  9216
#define ATTN_SMEM 73728

__global__ __launch_bounds__(256) void flash_attn_tc_kernel()
{
    extern __shared__ char smc[];
    const int qt = (int)(gridDim.x - 1 - blockIdx.x);   // heavy tiles first
    const int h = blockIdx.y, b = blockIdx.z;
    const int tid = threadIdx.x;
    const int wq = tid >> 5, lane = tid & 31;
    const int gid = lane >> 2, tig = lane & 3;
    const int g8 = lane >> 3, r8 = lane & 7;
    const int q0 = qt * 128;

    const uint32_t sm_u = smem_u32(smc);
    float* Qs = (float*)smc;                         // [128][68] f32, start only
    __half* Phi = (__half*)(smc + PHI_B);
    const __half* Vt = g_Vh + ((size_t)b * DHEAD + h) * DK * LK;

    const int ntiles = 2 * qt + 2;

    const uint32_t aPhi = sm_u + PHI_B +
        (uint32_t)((wq * 16 + r8 + (g8 & 1) * 8) * PSTR + (g8 >> 1) * 8) * 2;
    const uint32_t bfrag = (uint32_t)((r8 + (g8 >> 1) * 8) * PSTR + (g8 & 1) * 8) * 2;
    const uint32_t aK = sm_u + KS_B + bfrag;
    const uint32_t aV = sm_u + VS_B + bfrag;

    // --- K/V tile 0 (cp.async) ---
    {
#pragma unroll
        for (int i = 0; i < 2; i++) {
            int idx = i * 256 + tid;
            int row = idx >> 3, seg = idx & 7;
            const __half* kp = g_Kh + (size_t)(b * LK + row) * DEPTH + h * DK + seg * 8;
            const __half* vp = Vt + (size_t)row * LK + seg * 8;
            cp16(sm_u + KS_B + (uint32_t)(row * PSTR + seg * 8) * 2, kp);
            cp16(sm_u + VS_B + (uint32_t)(row * PSTR + seg * 8) * 2, vp);
        }
        cp_commit();
    }

    // --- stage Q (x fac) fp32 ---
    {
        const float fac = 0.125f;
#pragma unroll
        for (int i = 0; i < 8; i++) {
            int idx = i * 256 + tid;
            int row = idx >> 4, c4 = idx & 15;
            float4 v = *(const float4*)&g_Q[(size_t)(b * LQ + q0 + row) * DEPTH + h * DK + c4 * 4];
            float* d = &Qs[row * 68 + c4 * 4];
            d[0] = v.x * fac; d[1] = v.y * fac; d[2] = v.z * fac; d[3] = v.w * fac;
        }
    }
    __syncthreads();

    // --- extract Q hi/lo fragments (4 k16 chunks over d=64) ---
    uint32_t qhi[4][4], qlo[4][4];
    {
        const int r0 = wq * 16 + gid;
#pragma unroll
        for (int kc = 0; kc < 4; kc++) {
            float2 f0 = *(float2*)&Qs[r0 * 68 + kc * 16 + 2 * tig];
            float2 f1 = *(float2*)&Qs[(r0 + 8) * 68 + kc * 16 + 2 * tig];
            float2 f2 = *(float2*)&Qs[r0 * 68 + kc * 16 + 2 * tig + 8];
            float2 f3 = *(float2*)&Qs[(r0 + 8) * 68 + kc * 16 + 2 * tig + 8];
            split2(f0.x, f0.y, qhi[kc][0], qlo[kc][0]);
            split2(f1.x, f1.y, qhi[kc][1], qlo[kc][1]);
            split2(f2.x, f2.y, qhi[kc][2], qlo[kc][2]);
            split2(f3.x, f3.y, qhi[kc][3], qlo[kc][3]);
        }
    }
    __syncthreads();   // Qs region free for P

    float o[8][4];
#pragma unroll
    for (int nc = 0; nc < 8; nc++)
#pragma unroll
        for (int r = 0; r < 4; r++) o[nc][r] = 0.f;
    float m0 = -1e30f, m1 = -1e30f, l0 = 0.f, l1 = 0.f;

    const int qrow0 = q0 + wq * 16 + gid;
    const int qrow1 = qrow0 + 8;
    __half* PhiR0 = Phi + (wq * 16 + gid) * PSTR;
    __half* PhiR1 = PhiR0 + 8 * PSTR;

#pragma unroll 1
    for (int kt = 0; kt < ntiles; kt++) {
        cp_wait0();
        __syncthreads();
        const int cur = kt & 1;
        if (kt + 1 < ntiles) {
            const int k1 = (kt + 1) * 64, nb = (kt + 1) & 1;
#pragma unroll
            for (int i = 0; i < 2; i++) {
                int idx = i * 256 + tid;
                int row = idx >> 3, seg = idx & 7;
                const __half* kp = g_Kh + (size_t)(b * LK + k1 + row) * DEPTH + h * DK + seg * 8;
                const __half* vp = Vt + (size_t)row * LK + k1 + seg * 8;
                cp16(sm_u + KS_B + (uint32_t)(nb * KVSTG) + (uint32_t)(row * PSTR + seg * 8) * 2, kp);
                cp16(sm_u + VS_B + (uint32_t)(nb * KVSTG) + (uint32_t)(row * PSTR + seg * 8) * 2, vp);
            }
            cp_commit();
        }

        const uint32_t Kb = aK + (uint32_t)(cur * KVSTG);
        const uint32_t Vb = aV + (uint32_t)(cur * KVSTG);
        const int k0 = kt * 64;

        // ---- S = Q K^T (hi/lo chains) ----
        float s[8][4];
#pragma unroll
        for (int nc = 0; nc < 8; nc++)
#pragma unroll
            for (int r = 0; r < 4; r++) s[nc][r] = 0.f;
#pragma unroll
        for (int kc = 0; kc < 4; kc++) {
#pragma unroll
            for (int ncp = 0; ncp < 4; ncp++) {
                uint32_t t[4];
                ldmx4(t, Kb + (uint32_t)(ncp * 16 * PSTR + kc * 16) * 2);
                const int n0i = 2 * ncp, n1i = 2 * ncp + 1;
                mma_f16(s[n0i][0], s[n0i][1], s[n0i][2], s[n0i][3],
                        qhi[kc][0], qhi[kc][1], qhi[kc][2], qhi[kc][3], t[0], t[1]);
                mma_f16(s[n0i][0], s[n0i][1], s[n0i][2], s[n0i][3],
                        qlo[kc][0], qlo[kc][1], qlo[kc][2], qlo[kc][3], t[0], t[1]);
                mma_f16(s[n1i][0], s[n1i][1], s[n1i][2], s[n1i][3],
                        qhi[kc][0], qhi[kc][1], qhi[kc][2], qhi[kc][3], t[2], t[3]);
                mma_f16(s[n1i][0], s[n1i][1], s[n1i][2], s[n1i][3],
                        qlo[kc][0], qlo[kc][1], qlo[kc][2], qlo[kc][3], t[2], t[3]);
            }
        }

        // ---- causal mask (diagonal tiles only) ----
        if (kt >= 2 * qt) {
#pragma unroll
            for (int nc = 0; nc < 8; nc++) {
                int col = k0 + nc * 8 + 2 * tig;
                if (col > qrow0)     s[nc][0] = -1e30f;
                if (col + 1 > qrow0) s[nc][1] = -1e30f;
                if (col > qrow1)     s[nc][2] = -1e30f;
                if (col + 1 > qrow1) s[nc][3] = -1e30f;
            }
        }

        // ---- online softmax ----
        float mx0 = -1e30f, mx1 = -1e30f;
#pragma unroll
        for (int nc = 0; nc < 8; nc++) {
            mx0 = fmaxf(mx0, fmaxf(s[nc][0], s[nc][1]));
            mx1 = fmaxf(mx1, fmaxf(s[nc][2], s[nc][3]));
        }
        mx0 = fmaxf(mx0, __shfl_xor_sync(0xffffffffu, mx0, 1));
        mx0 = fmaxf(mx0, __shfl_xor_sync(0xffffffffu, mx0, 2));
        mx1 = fmaxf(mx1, __shfl_xor_sync(0xffffffffu, mx1, 1));
        mx1 = fmaxf(mx1, __shfl_xor_sync(0xffffffffu, mx1, 2));
        float mn0 = fmaxf(m0, mx0), mn1 = fmaxf(m1, mx1);
        float c0 = __expf(m0 - mn0), c1 = __expf(m1 - mn1);
        m0 = mn0; m1 = mn1;
        l0 *= c0; l1 *= c1;
#pragma unroll
        for (int nc = 0; nc < 8; nc++) {
            o[nc][0] *= c0; o[nc][1] *= c0;
            o[nc][2] *= c1; o[nc][3] *= c1;
        }
        float ls0 = 0.f, ls1 = 0.f;
#pragma unroll
        for (int nc = 0; nc < 8; nc++) {
            float p0 = __expf(s[nc][0] - mn0);
            float p1 = __expf(s[nc][1] - mn0);
            float p2 = __expf(s[nc][2] - mn1);
            float p3 = __expf(s[nc][3] - mn1);
            ls0 += p0 + p1; ls1 += p2 + p3;
            __half2 h0 = __floats2half2_rn(p0, p1);
            __half2 h1 = __floats2half2_rn(p2, p3);
            *(uint32_t*)&PhiR0[nc * 8 + 2 * tig] = *(uint32_t*)&h0;
            *(uint32_t*)&PhiR1[nc * 8 + 2 * tig] = *(uint32_t*)&h1;
        }
        l0 += ls0; l1 += ls1;
        __syncwarp();

        // ---- O += P V (single chain): 4 kc (keys) x 4 ncp (dims) ----
#pragma unroll
        for (int kc = 0; kc < 4; kc++) {
            uint32_t phi[4];
            ldmx4(phi, aPhi + (uint32_t)(kc * 16) * 2);
#pragma unroll
            for (int ncp = 0; ncp < 4; ncp++) {
                uint32_t t[4];
                ldmx4(t, Vb + (uint32_t)(ncp * 16 * PSTR + kc * 16) * 2);
                const int n0i = 2 * ncp, n1i = 2 * ncp + 1;
                mma_f16(o[n0i][0], o[n0i][1], o[n0i][2], o[n0i][3],
                        phi[0], phi[1], phi[2], phi[3], t[0], t[1]);
                mma_f16(o[n1i][0], o[n1i][1], o[n1i][2], o[n1i][3],
                        phi[0], phi[1], phi[2], phi[3], t[2], t[3]);
            }
        }
    }

    // ---- finalize: reduce l, normalize, store fp16 ----
    l0 += __shfl_xor_sync(0xffffffffu, l0, 1);
    l0 += __shfl_xor_sync(0xffffffffu, l0, 2);
    l1 += __shfl_xor_sync(0xffffffffu, l1, 1);
    l1 += __shfl_xor_sync(0xffffffffu, l1, 2);
    const float inv0 = 1.f / l0, inv1 = 1.f / l1;

    __half* o0 = g_Oh + (size_t)(b * LQ + qrow0) * DEPTH + h * DK;
    __half* o1 = g_Oh + (size_t)(b * LQ + qrow1) * DEPTH + h * DK;
#pragma unroll
    for (int nc = 0; nc < 8; nc++) {
        __half2 r0 = __floats2half2_rn(o[nc][0] * inv0, o[nc][1] * inv0);
        __half2 r1 = __floats2half2_rn(o[nc][2] * inv1, o[nc][3] * inv1);
        *(uint32_t*)&o0[nc * 8 + 2 * tig] = *(uint32_t*)&r0;
        *(uint32_t*)&o1[nc * 8 + 2 * tig] = *(uint32_t*)&r1;
    }
}

// ---------------------------------------------------------------------------
// Launch. Captured profile = my launch index 3 (0-based) -> attention.
// ---------------------------------------------------------------------------
extern "C" void kernel_launch(void* const* d_in, const int* in_sizes, int n_in,
                              void* d_out, int out_size)
{
    const float* x  = (const float*)d_in[0];
    const float* y  = (const float*)d_in[1];
    // d_in[2] = causal mask — implicit
    const float* Wq = (const float*)d_in[3];
    const float* bq = (const float*)d_in[4];
    const float* Wk = (const float*)d_in[5];
    const float* bk = (const float*)d_in[6];
    const float* Wv = (const float*)d_in[7];
    const float* bv = (const float*)d_in[8];
    const float* Wo = (const float*)d_in[9];
    const float* bo = (const float*)d_in[10];
    float* out = (float*)d_out;

    cudaFuncSetAttribute(gemm_tc_kernel,
                         cudaFuncAttributeMaxDynamicSharedMemorySize, GEMM_SMEM);
    cudaFuncSetAttribute(gemm_kv_kernel,
                         cudaFuncAttributeMaxDynamicSharedMemorySize, GEMM_SMEM);
    cudaFuncSetAttribute(flash_attn_tc_kernel,
                         cudaFuncAttributeMaxDynamicSharedMemorySize, ATTN_SMEM);

    prep_kernel<<<12288, 256>>>(x, y, Wq, Wk, Wv, Wo);                 // 0

    dim3 ggrid(DEPTH / 128, MROWS / 128);        // (8, 32)
    gemm_tc_kernel<<<ggrid, 256, GEMM_SMEM>>>(bq, nullptr, 0, 0, 0);   // 1: -> g_Q (f32)

    dim3 kvgrid(DEPTH / 128, MROWS / 128, 2);    // (8, 32, 2) fused K+V
    gemm_kv_kernel<<<kvgrid, 256, GEMM_SMEM>>>(bk, bv);                // 2: -> g_Kh, g_Vh^T

    dim3 agrid(LQ / 128, DHEAD, NB);
    flash_attn_tc_kernel<<<agrid, 256, ATTN_SMEM>>>();                 // 3: -> g_Oh  [captured]

    gemm_tc_kernel<<<ggrid, 256, GEMM_SMEM>>>(bo, out, 2, 3, 3);       // 4: -> out
}